// round 12
// baseline (speedup 1.0000x reference)
#include <cuda_runtime.h>
#include <cuda_bf16.h>
#include <cstdint>

// S4D diagonal SSM via split-precision bf16 mma.sync (HMMA, sm_80+ -> legal on sm_100).
// Factor l = 64k + j (k in [0,32), j in [0,64)):
//   out[h,64k+j] = sum_n ( Bre[k,n]*Are[n,j] - Bim[k,n]*Aim[n,j] ) = D[j][k]
//   D[128][32] = Aop[128x128] . Bop[32x128]^T,  reduction dim = 2n interleaved (re,im)
// Aop rows 0-63 = bf16_hi(Are,Aim), rows 64-127 = bf16_lo residual.
// Bop hi/lo tiles rows k: (Bre, -Bim). Two accumulating passes => D=(Ah+Al)(Bh+Bl)
// split across row halves; epilogue out[j][k] = D[j][k] + D[j+64][k]. Err ~2^-18.

#define HDIM 1024
#define NDIM 64
#define LLEN 2048

#define AROWB 272      // A row stride bytes (128 bf16 cols + 8 pad) ; 68 words = 4 mod 32
#define BROWB 272      // B row stride bytes
#define SM_A   0                        // 128 x AROWB = 34816 B (reused as fp32 stage)
#define SM_BH  (128*AROWB)              // 32 x BROWB = 8704 B
#define SM_BL  (SM_BH + 32*BROWB)
#define SM_TOTAL (SM_BL + 32*BROWB)     // 52224 B

struct c2 { float re, im; };
__device__ __forceinline__ c2 cmul(c2 a, c2 b) {
    return { fmaf(a.re, b.re, -a.im*b.im), fmaf(a.re, b.im, a.im*b.re) };
}

__device__ __forceinline__ void mma16816(float* c, const uint32_t* a, const uint32_t* b) {
    asm volatile(
        "mma.sync.aligned.m16n8k16.row.col.f32.bf16.bf16.f32 "
        "{%0,%1,%2,%3}, {%4,%5,%6,%7}, {%8,%9}, {%0,%1,%2,%3};"
        : "+f"(c[0]), "+f"(c[1]), "+f"(c[2]), "+f"(c[3])
        : "r"(a[0]), "r"(a[1]), "r"(a[2]), "r"(a[3]), "r"(b[0]), "r"(b[1]));
}

__global__ __launch_bounds__(128) void ssk_diag_kernel(
    const float* __restrict__ log_dt,
    const float* __restrict__ log_w_real,
    const float* __restrict__ w_imag,
    const float* __restrict__ C_re,
    const float* __restrict__ C_im,
    float* __restrict__ out)
{
    extern __shared__ char smem[];
    const int h   = blockIdx.x;
    const int tid = threadIdx.x;
    const int wid = tid >> 5;
    const int lid = tid & 31;

    // ------------- Phase 1: build bf16 hi/lo operand tiles --------------------------
    {
        const int n    = tid & 63;
        const int half = tid >> 6;

        const float dtv = expf(log_dt[h]);
        const float wre = -expf(log_w_real[h*NDIM + n]);
        const float wim = w_imag[h*NDIM + n];
        const float er  = expf(wre * dtv);
        float s, c; sincosf(wim * dtv, &s, &c);
        const c2 z = { er*c, er*s };

        // cmod = 2 * C * (z - 1) / w  (fold the output factor of 2)
        const float nre = z.re - 1.0f, nim = z.im;
        const float inv = 1.0f / (wre*wre + wim*wim);
        const float tre = (nre*wre + nim*wim) * inv;
        const float tim = (nim*wre - nre*wim) * inv;
        const float cr = C_re[h*NDIM + n], ci = C_im[h*NDIM + n];
        const c2 cm = { 2.0f*(cr*tre - ci*tim), 2.0f*(cr*tim + ci*tre) };

        // power ladder by squaring
        const c2 z2    = cmul(z,    z);
        const c2 z4    = cmul(z2,   z2);
        const c2 z8    = cmul(z4,   z4);
        const c2 z16   = cmul(z8,   z8);
        const c2 z32   = cmul(z16,  z16);
        const c2 z64   = cmul(z32,  z32);
        const c2 z128  = cmul(z64,  z64);
        const c2 z256  = cmul(z128, z128);
        const c2 z512  = cmul(z256, z256);
        const c2 z1024 = cmul(z512, z512);

        // A operand: row j (hi) / j+64 (lo), cols (2n, 2n+1) = (Are, Aim)
        c2 a = half ? z32 : c2{1.0f, 0.0f};
        #pragma unroll
        for (int jj = 0; jj < 32; jj++) {
            const int j = 32*half + jj;
            const __nv_bfloat16 hr = __float2bfloat16_rn(a.re);
            const __nv_bfloat16 hi = __float2bfloat16_rn(a.im);
            const float lr = a.re - __bfloat162float(hr);
            const float li = a.im - __bfloat162float(hi);
            *reinterpret_cast<__nv_bfloat162*>(smem + SM_A + j*AROWB + 4*n) =
                __nv_bfloat162(hr, hi);
            *reinterpret_cast<__nv_bfloat162*>(smem + SM_A + (j+64)*AROWB + 4*n) =
                __floats2bfloat162_rn(lr, li);
            a = cmul(a, z);
        }

        // B operand: row k, cols (2n, 2n+1) = (Bre, -Bim); hi and lo tiles
        c2 b = half ? cmul(cm, z1024) : cm;
        #pragma unroll
        for (int kk = 0; kk < 16; kk++) {
            const int k = 16*half + kk;
            const float bre = b.re, bim = -b.im;
            const __nv_bfloat16 hr = __float2bfloat16_rn(bre);
            const __nv_bfloat16 hi = __float2bfloat16_rn(bim);
            *reinterpret_cast<__nv_bfloat162*>(smem + SM_BH + k*BROWB + 4*n) =
                __nv_bfloat162(hr, hi);
            *reinterpret_cast<__nv_bfloat162*>(smem + SM_BL + k*BROWB + 4*n) =
                __floats2bfloat162_rn(bre - __bfloat162float(hr),
                                      bim - __bfloat162float(hi));
            b = cmul(b, z64);
        }
    }
    __syncthreads();

    // ------------- Phase 2: mma.sync contraction ------------------------------------
    // Warp w: M rows [32w, 32w+32). 2 m16 tiles x 4 n8 tiles x 8 k16 steps x 2 passes.
    const int g = lid >> 2;     // 0..7  (group / row-in-tile)
    const int t = lid & 3;      // 0..3  (thread-in-group / col pair)
    const int mbase = wid * 32;

    float acc[2][4][4];
    #pragma unroll
    for (int mt = 0; mt < 2; mt++)
        #pragma unroll
        for (int nt = 0; nt < 4; nt++)
            #pragma unroll
            for (int i = 0; i < 4; i++) acc[mt][nt][i] = 0.0f;

    #pragma unroll
    for (int s = 0; s < 8; s++) {
        const int k0 = 16*s;

        uint32_t af[2][4];
        #pragma unroll
        for (int mt = 0; mt < 2; mt++) {
            const int r = mbase + mt*16 + g;
            af[mt][0] = *reinterpret_cast<const uint32_t*>(smem + SM_A + r*AROWB     + (k0 + 2*t)*2);
            af[mt][1] = *reinterpret_cast<const uint32_t*>(smem + SM_A + (r+8)*AROWB + (k0 + 2*t)*2);
            af[mt][2] = *reinterpret_cast<const uint32_t*>(smem + SM_A + r*AROWB     + (k0 + 2*t + 8)*2);
            af[mt][3] = *reinterpret_cast<const uint32_t*>(smem + SM_A + (r+8)*AROWB + (k0 + 2*t + 8)*2);
        }
        uint32_t bh[4][2], bl[4][2];
        #pragma unroll
        for (int nt = 0; nt < 4; nt++) {
            const int n = nt*8 + g;
            bh[nt][0] = *reinterpret_cast<const uint32_t*>(smem + SM_BH + n*BROWB + (k0 + 2*t)*2);
            bh[nt][1] = *reinterpret_cast<const uint32_t*>(smem + SM_BH + n*BROWB + (k0 + 2*t + 8)*2);
            bl[nt][0] = *reinterpret_cast<const uint32_t*>(smem + SM_BL + n*BROWB + (k0 + 2*t)*2);
            bl[nt][1] = *reinterpret_cast<const uint32_t*>(smem + SM_BL + n*BROWB + (k0 + 2*t + 8)*2);
        }

        #pragma unroll
        for (int mt = 0; mt < 2; mt++)
            #pragma unroll
            for (int nt = 0; nt < 4; nt++) {
                mma16816(acc[mt][nt], af[mt], bh[nt]);
                mma16816(acc[mt][nt], af[mt], bl[nt]);
            }
    }

    // ------------- Epilogue: stage D (fp32) in retired A region, add halves --------
    __syncthreads();   // all A/B reads complete before overwriting A region
    float* stage = reinterpret_cast<float*>(smem + SM_A);   // [128][33]
    #pragma unroll
    for (int mt = 0; mt < 2; mt++) {
        const int r = mbase + mt*16 + g;
        #pragma unroll
        for (int nt = 0; nt < 4; nt++) {
            const int cb = nt*8 + 2*t;
            stage[r*33 + cb]       = acc[mt][nt][0];
            stage[r*33 + cb + 1]   = acc[mt][nt][1];
            stage[(r+8)*33 + cb]     = acc[mt][nt][2];
            stage[(r+8)*33 + cb + 1] = acc[mt][nt][3];
        }
    }
    __syncthreads();

    // out[h, 64k + j] = stage[j][k] + stage[j+64][k]
    {
        const int k  = tid >> 2;       // 0..31
        const int jg = tid & 3;        // 0..3 -> j base = 16*jg
        float* po = out + (size_t)h*LLEN + k*64 + jg*16;
        #pragma unroll
        for (int q = 0; q < 4; q++) {
            const int j = jg*16 + q*4;
            float4 v;
            v.x = stage[(j+0)*33 + k] + stage[(j+64)*33 + k];
            v.y = stage[(j+1)*33 + k] + stage[(j+65)*33 + k];
            v.z = stage[(j+2)*33 + k] + stage[(j+66)*33 + k];
            v.w = stage[(j+3)*33 + k] + stage[(j+67)*33 + k];
            *reinterpret_cast<float4*>(po + q*4) = v;
        }
    }
}

extern "C" void kernel_launch(void* const* d_in, const int* in_sizes, int n_in,
                              void* d_out, int out_size)
{
    const float* log_dt     = (const float*)d_in[0];
    const float* log_w_real = (const float*)d_in[1];
    const float* w_imag     = (const float*)d_in[2];
    const float* C_re       = (const float*)d_in[3];
    const float* C_im       = (const float*)d_in[4];
    float* out = (float*)d_out;

    cudaFuncSetAttribute(ssk_diag_kernel,
                         cudaFuncAttributeMaxDynamicSharedMemorySize, SM_TOTAL);

    ssk_diag_kernel<<<HDIM, 128, SM_TOTAL>>>(log_dt, log_w_real, w_imag,
                                             C_re, C_im, out);
}

// round 13
// speedup vs baseline: 1.0017x; 1.0017x over previous
#include <cuda_runtime.h>
#include <cuda_bf16.h>
#include <cstdint>

// S4D diagonal SSM via split-precision bf16 mma.sync (HMMA, sm_80+ -> legal on sm_100).
// Factor l = 64k + j (k in [0,32), j in [0,64)):
//   out[h,64k+j] = sum_n ( Bre[k,n]*Are[n,j] - Bim[k,n]*Aim[n,j] ) = D[j][k]
//   D[128][32] = Aop[128x128] . Bop[32x128]^T,  reduction dim = 2n interleaved (re,im)
// Aop rows 0-63 = bf16_hi(Are,Aim), rows 64-127 = bf16_lo residual.
// Bop hi/lo tiles rows k: (Bre, -Bim). Two accumulating passes => D=(Ah+Al)(Bh+Bl)
// split across row halves; epilogue out[j][k] = D[j][k] + D[j+64][k]. Err ~2^-18.

#define HDIM 1024
#define NDIM 64
#define LLEN 2048

#define AROWB 272      // A row stride bytes (128 bf16 cols + 8 pad) ; 68 words = 4 mod 32
#define BROWB 272      // B row stride bytes
#define SM_A   0                        // 128 x AROWB = 34816 B (reused as fp32 stage)
#define SM_BH  (128*AROWB)              // 32 x BROWB = 8704 B
#define SM_BL  (SM_BH + 32*BROWB)
#define SM_TOTAL (SM_BL + 32*BROWB)     // 52224 B

struct c2 { float re, im; };
__device__ __forceinline__ c2 cmul(c2 a, c2 b) {
    return { fmaf(a.re, b.re, -a.im*b.im), fmaf(a.re, b.im, a.im*b.re) };
}

__device__ __forceinline__ void mma16816(float* c, const uint32_t* a, const uint32_t* b) {
    asm volatile(
        "mma.sync.aligned.m16n8k16.row.col.f32.bf16.bf16.f32 "
        "{%0,%1,%2,%3}, {%4,%5,%6,%7}, {%8,%9}, {%0,%1,%2,%3};"
        : "+f"(c[0]), "+f"(c[1]), "+f"(c[2]), "+f"(c[3])
        : "r"(a[0]), "r"(a[1]), "r"(a[2]), "r"(a[3]), "r"(b[0]), "r"(b[1]));
}

__global__ __launch_bounds__(128) void ssk_diag_kernel(
    const float* __restrict__ log_dt,
    const float* __restrict__ log_w_real,
    const float* __restrict__ w_imag,
    const float* __restrict__ C_re,
    const float* __restrict__ C_im,
    float* __restrict__ out)
{
    extern __shared__ char smem[];
    const int h   = blockIdx.x;
    const int tid = threadIdx.x;
    const int wid = tid >> 5;
    const int lid = tid & 31;

    // ------------- Phase 1: build bf16 hi/lo operand tiles --------------------------
    {
        const int n    = tid & 63;
        const int half = tid >> 6;

        const float dtv = expf(log_dt[h]);
        const float wre = -expf(log_w_real[h*NDIM + n]);
        const float wim = w_imag[h*NDIM + n];
        const float er  = expf(wre * dtv);
        float s, c; sincosf(wim * dtv, &s, &c);
        const c2 z = { er*c, er*s };

        // cmod = 2 * C * (z - 1) / w  (fold the output factor of 2)
        const float nre = z.re - 1.0f, nim = z.im;
        const float inv = 1.0f / (wre*wre + wim*wim);
        const float tre = (nre*wre + nim*wim) * inv;
        const float tim = (nim*wre - nre*wim) * inv;
        const float cr = C_re[h*NDIM + n], ci = C_im[h*NDIM + n];
        const c2 cm = { 2.0f*(cr*tre - ci*tim), 2.0f*(cr*tim + ci*tre) };

        // power ladder by squaring
        const c2 z2    = cmul(z,    z);
        const c2 z4    = cmul(z2,   z2);
        const c2 z8    = cmul(z4,   z4);
        const c2 z16   = cmul(z8,   z8);
        const c2 z32   = cmul(z16,  z16);
        const c2 z64   = cmul(z32,  z32);
        const c2 z128  = cmul(z64,  z64);
        const c2 z256  = cmul(z128, z128);
        const c2 z512  = cmul(z256, z256);
        const c2 z1024 = cmul(z512, z512);

        // A operand: row j (hi) / j+64 (lo), cols (2n, 2n+1) = (Are, Aim)
        c2 a = half ? z32 : c2{1.0f, 0.0f};
        #pragma unroll
        for (int jj = 0; jj < 32; jj++) {
            const int j = 32*half + jj;
            const __nv_bfloat16 hr = __float2bfloat16_rn(a.re);
            const __nv_bfloat16 hi = __float2bfloat16_rn(a.im);
            const float lr = a.re - __bfloat162float(hr);
            const float li = a.im - __bfloat162float(hi);
            *reinterpret_cast<__nv_bfloat162*>(smem + SM_A + j*AROWB + 4*n) =
                __nv_bfloat162(hr, hi);
            *reinterpret_cast<__nv_bfloat162*>(smem + SM_A + (j+64)*AROWB + 4*n) =
                __floats2bfloat162_rn(lr, li);
            a = cmul(a, z);
        }

        // B operand: row k, cols (2n, 2n+1) = (Bre, -Bim); hi and lo tiles
        c2 b = half ? cmul(cm, z1024) : cm;
        #pragma unroll
        for (int kk = 0; kk < 16; kk++) {
            const int k = 16*half + kk;
            const float bre = b.re, bim = -b.im;
            const __nv_bfloat16 hr = __float2bfloat16_rn(bre);
            const __nv_bfloat16 hi = __float2bfloat16_rn(bim);
            *reinterpret_cast<__nv_bfloat162*>(smem + SM_BH + k*BROWB + 4*n) =
                __nv_bfloat162(hr, hi);
            *reinterpret_cast<__nv_bfloat162*>(smem + SM_BL + k*BROWB + 4*n) =
                __floats2bfloat162_rn(bre - __bfloat162float(hr),
                                      bim - __bfloat162float(hi));
            b = cmul(b, z64);
        }
    }
    __syncthreads();

    // ------------- Phase 2: mma.sync contraction ------------------------------------
    // Warp w: M rows [32w, 32w+32). 2 m16 tiles x 4 n8 tiles x 8 k16 steps x 2 passes.
    const int g = lid >> 2;     // 0..7  (group / row-in-tile)
    const int t = lid & 3;      // 0..3  (thread-in-group / col pair)
    const int mbase = wid * 32;

    float acc[2][4][4];
    #pragma unroll
    for (int mt = 0; mt < 2; mt++)
        #pragma unroll
        for (int nt = 0; nt < 4; nt++)
            #pragma unroll
            for (int i = 0; i < 4; i++) acc[mt][nt][i] = 0.0f;

    #pragma unroll
    for (int s = 0; s < 8; s++) {
        const int k0 = 16*s;

        uint32_t af[2][4];
        #pragma unroll
        for (int mt = 0; mt < 2; mt++) {
            const int r = mbase + mt*16 + g;
            af[mt][0] = *reinterpret_cast<const uint32_t*>(smem + SM_A + r*AROWB     + (k0 + 2*t)*2);
            af[mt][1] = *reinterpret_cast<const uint32_t*>(smem + SM_A + (r+8)*AROWB + (k0 + 2*t)*2);
            af[mt][2] = *reinterpret_cast<const uint32_t*>(smem + SM_A + r*AROWB     + (k0 + 2*t + 8)*2);
            af[mt][3] = *reinterpret_cast<const uint32_t*>(smem + SM_A + (r+8)*AROWB + (k0 + 2*t + 8)*2);
        }
        uint32_t bh[4][2], bl[4][2];
        #pragma unroll
        for (int nt = 0; nt < 4; nt++) {
            const int n = nt*8 + g;
            bh[nt][0] = *reinterpret_cast<const uint32_t*>(smem + SM_BH + n*BROWB + (k0 + 2*t)*2);
            bh[nt][1] = *reinterpret_cast<const uint32_t*>(smem + SM_BH + n*BROWB + (k0 + 2*t + 8)*2);
            bl[nt][0] = *reinterpret_cast<const uint32_t*>(smem + SM_BL + n*BROWB + (k0 + 2*t)*2);
            bl[nt][1] = *reinterpret_cast<const uint32_t*>(smem + SM_BL + n*BROWB + (k0 + 2*t + 8)*2);
        }

        #pragma unroll
        for (int mt = 0; mt < 2; mt++)
            #pragma unroll
            for (int nt = 0; nt < 4; nt++) {
                mma16816(acc[mt][nt], af[mt], bh[nt]);
                mma16816(acc[mt][nt], af[mt], bl[nt]);
            }
    }

    // ------------- Epilogue: stage D (fp32) in retired A region, add halves --------
    __syncthreads();   // all A/B reads complete before overwriting A region
    float* stage = reinterpret_cast<float*>(smem + SM_A);   // [128][33]
    #pragma unroll
    for (int mt = 0; mt < 2; mt++) {
        const int r = mbase + mt*16 + g;
        #pragma unroll
        for (int nt = 0; nt < 4; nt++) {
            const int cb = nt*8 + 2*t;
            stage[r*33 + cb]       = acc[mt][nt][0];
            stage[r*33 + cb + 1]   = acc[mt][nt][1];
            stage[(r+8)*33 + cb]     = acc[mt][nt][2];
            stage[(r+8)*33 + cb + 1] = acc[mt][nt][3];
        }
    }
    __syncthreads();

    // out[h, 64k + j] = stage[j][k] + stage[j+64][k]
    {
        const int k  = tid >> 2;       // 0..31
        const int jg = tid & 3;        // 0..3 -> j base = 16*jg
        float* po = out + (size_t)h*LLEN + k*64 + jg*16;
        #pragma unroll
        for (int q = 0; q < 4; q++) {
            const int j = jg*16 + q*4;
            float4 v;
            v.x = stage[(j+0)*33 + k] + stage[(j+64)*33 + k];
            v.y = stage[(j+1)*33 + k] + stage[(j+65)*33 + k];
            v.z = stage[(j+2)*33 + k] + stage[(j+66)*33 + k];
            v.w = stage[(j+3)*33 + k] + stage[(j+67)*33 + k];
            *reinterpret_cast<float4*>(po + q*4) = v;
        }
    }
}

extern "C" void kernel_launch(void* const* d_in, const int* in_sizes, int n_in,
                              void* d_out, int out_size)
{
    const float* log_dt     = (const float*)d_in[0];
    const float* log_w_real = (const float*)d_in[1];
    const float* w_imag     = (const float*)d_in[2];
    const float* C_re       = (const float*)d_in[3];
    const float* C_im       = (const float*)d_in[4];
    float* out = (float*)d_out;

    cudaFuncSetAttribute(ssk_diag_kernel,
                         cudaFuncAttributeMaxDynamicSharedMemorySize, SM_TOTAL);

    ssk_diag_kernel<<<HDIM, 128, SM_TOTAL>>>(log_dt, log_w_real, w_imag,
                                             C_re, C_im, out);
}

// round 14
// speedup vs baseline: 1.2543x; 1.2522x over previous
#include <cuda_runtime.h>
#include <cuda_bf16.h>
#include <cstdint>

// S4D diagonal SSM via split-precision bf16 mma.sync (HMMA).
// Factor l = 64k + j (k in [0,32), j in [0,64)):
//   out[h,64k+j] = sum_n ( Bre[k,n]*Are[n,j] - Bim[k,n]*Aim[n,j] )
// GEMM orientation (R14): D2[64][64] = Bop[64x128] . Aop[64x128]^T
//   reduction dim = 2n interleaved (re,im)
//   Bop rows 0-31 = bf16_hi(Bre,-Bim) for k, rows 32-63 = bf16_lo residual.
//   Aop hi/lo tables = the two accumulating passes.
//   => D2[k][j] = Bh[k](Ah+Al)[j],  D2[k+32][j] = Bl[k](Ah+Al)[j]
//   out[64k+j] = D2[k][j] + D2[k+32][j]  -- both terms live in the SAME thread's
//   fragments (warp owns m-tile pair 16mw and 16mw+32) -> register FADD epilogue,
//   no smem staging, no post-MMA barrier, STG.64 stores.

#define HDIM 1024
#define NDIM 64
#define LLEN 2048

#define ROWB 272      // row stride bytes: 128 bf16 + 8 pad (68 words = 4 mod 32 -> conflict-free frags)
#define SM_BOP 0                      // 64 x ROWB = 17408 B
#define SM_AH  (64*ROWB)              // 17408 B
#define SM_AL  (SM_AH + 64*ROWB)      // 17408 B
#define SM_TOTAL (SM_AL + 64*ROWB)    // 52224 B

struct c2 { float re, im; };
__device__ __forceinline__ c2 cmul(c2 a, c2 b) {
    return { fmaf(a.re, b.re, -a.im*b.im), fmaf(a.re, b.im, a.im*b.re) };
}

__device__ __forceinline__ void mma16816(float* c, const uint32_t* a, const uint32_t* b) {
    asm volatile(
        "mma.sync.aligned.m16n8k16.row.col.f32.bf16.bf16.f32 "
        "{%0,%1,%2,%3}, {%4,%5,%6,%7}, {%8,%9}, {%0,%1,%2,%3};"
        : "+f"(c[0]), "+f"(c[1]), "+f"(c[2]), "+f"(c[3])
        : "r"(a[0]), "r"(a[1]), "r"(a[2]), "r"(a[3]), "r"(b[0]), "r"(b[1]));
}

__global__ __launch_bounds__(128) void ssk_diag_kernel(
    const float* __restrict__ log_dt,
    const float* __restrict__ log_w_real,
    const float* __restrict__ w_imag,
    const float* __restrict__ C_re,
    const float* __restrict__ C_im,
    float* __restrict__ out)
{
    extern __shared__ char smem[];
    const int h   = blockIdx.x;
    const int tid = threadIdx.x;
    const int wid = tid >> 5;
    const int lid = tid & 31;

    // ------------- Phase 1: build bf16 hi/lo operand tiles --------------------------
    {
        const int n    = tid & 63;
        const int half = tid >> 6;

        const float dtv = expf(log_dt[h]);
        const float wre = -expf(log_w_real[h*NDIM + n]);
        const float wim = w_imag[h*NDIM + n];
        const float er  = expf(wre * dtv);
        float s, c; sincosf(wim * dtv, &s, &c);
        const c2 z = { er*c, er*s };

        // cmod = 2 * C * (z - 1) / w  (fold the output factor of 2)
        const float nre = z.re - 1.0f, nim = z.im;
        const float inv = 1.0f / (wre*wre + wim*wim);
        const float tre = (nre*wre + nim*wim) * inv;
        const float tim = (nim*wre - nre*wim) * inv;
        const float cr = C_re[h*NDIM + n], ci = C_im[h*NDIM + n];
        const c2 cm = { 2.0f*(cr*tre - ci*tim), 2.0f*(cr*tim + ci*tre) };

        // power ladder by squaring
        const c2 z2    = cmul(z,    z);
        const c2 z4    = cmul(z2,   z2);
        const c2 z8    = cmul(z4,   z4);
        const c2 z16   = cmul(z8,   z8);
        const c2 z32   = cmul(z16,  z16);
        const c2 z64   = cmul(z32,  z32);
        const c2 z128  = cmul(z64,  z64);
        const c2 z256  = cmul(z128, z128);
        const c2 z512  = cmul(z256, z256);
        const c2 z1024 = cmul(z512, z512);

        // Aop: row j, cols (2n,2n+1) = (Are, Aim); hi table + lo residual table
        c2 a = half ? z32 : c2{1.0f, 0.0f};
        #pragma unroll
        for (int jj = 0; jj < 32; jj++) {
            const int j = 32*half + jj;
            const __nv_bfloat16 hr = __float2bfloat16_rn(a.re);
            const __nv_bfloat16 hi = __float2bfloat16_rn(a.im);
            *reinterpret_cast<__nv_bfloat162*>(smem + SM_AH + j*ROWB + 4*n) =
                __nv_bfloat162(hr, hi);
            *reinterpret_cast<__nv_bfloat162*>(smem + SM_AL + j*ROWB + 4*n) =
                __floats2bfloat162_rn(a.re - __bfloat162float(hr),
                                      a.im - __bfloat162float(hi));
            a = cmul(a, z);
        }

        // Bop: row k (hi) / k+32 (lo), cols (2n,2n+1) = (Bre, -Bim)
        c2 b = half ? cmul(cm, z1024) : cm;
        #pragma unroll
        for (int kk = 0; kk < 16; kk++) {
            const int k = 16*half + kk;
            const float bre = b.re, bim = -b.im;
            const __nv_bfloat16 hr = __float2bfloat16_rn(bre);
            const __nv_bfloat16 hi = __float2bfloat16_rn(bim);
            *reinterpret_cast<__nv_bfloat162*>(smem + SM_BOP + k*ROWB + 4*n) =
                __nv_bfloat162(hr, hi);
            *reinterpret_cast<__nv_bfloat162*>(smem + SM_BOP + (k+32)*ROWB + 4*n) =
                __floats2bfloat162_rn(bre - __bfloat162float(hr),
                                      bim - __bfloat162float(hi));
            b = cmul(b, z64);
        }
    }
    __syncthreads();

    // ------------- Phase 2: mma.sync. Warp (mw,nw): mw = wid&1, nw = wid>>1 --------
    // M-side (Bop): m-tile pair rows 16mw (hi) and 16mw+32 (lo).
    // N-side (Aop): 4 n8 tiles covering j = 32nw .. 32nw+31; hi/lo via 2 passes.
    const int g  = lid >> 2;    // 0..7
    const int t  = lid & 3;     // 0..3
    const int mw = wid & 1;
    const int nw = wid >> 1;

    float acc[2][4][4];         // [mt][nt][c]
    #pragma unroll
    for (int mt = 0; mt < 2; mt++)
        #pragma unroll
        for (int nt = 0; nt < 4; nt++)
            #pragma unroll
            for (int i = 0; i < 4; i++) acc[mt][nt][i] = 0.0f;

    #pragma unroll
    for (int s = 0; s < 8; s++) {
        const int kb0 = (16*s + 2*t) * 2;        // byte offset of k-pair lo
        const int kb1 = (16*s + 2*t + 8) * 2;

        uint32_t af[2][4];
        #pragma unroll
        for (int mt = 0; mt < 2; mt++) {
            const int r = 16*mw + 32*mt + g;
            af[mt][0] = *reinterpret_cast<const uint32_t*>(smem + SM_BOP + r*ROWB     + kb0);
            af[mt][1] = *reinterpret_cast<const uint32_t*>(smem + SM_BOP + (r+8)*ROWB + kb0);
            af[mt][2] = *reinterpret_cast<const uint32_t*>(smem + SM_BOP + r*ROWB     + kb1);
            af[mt][3] = *reinterpret_cast<const uint32_t*>(smem + SM_BOP + (r+8)*ROWB + kb1);
        }
        uint32_t bh[4][2], bl[4][2];
        #pragma unroll
        for (int nt = 0; nt < 4; nt++) {
            const int j = 32*nw + 8*nt + g;
            bh[nt][0] = *reinterpret_cast<const uint32_t*>(smem + SM_AH + j*ROWB + kb0);
            bh[nt][1] = *reinterpret_cast<const uint32_t*>(smem + SM_AH + j*ROWB + kb1);
            bl[nt][0] = *reinterpret_cast<const uint32_t*>(smem + SM_AL + j*ROWB + kb0);
            bl[nt][1] = *reinterpret_cast<const uint32_t*>(smem + SM_AL + j*ROWB + kb1);
        }

        #pragma unroll
        for (int mt = 0; mt < 2; mt++)
            #pragma unroll
            for (int nt = 0; nt < 4; nt++) {
                mma16816(acc[mt][nt], af[mt], bh[nt]);
                mma16816(acc[mt][nt], af[mt], bl[nt]);
            }
    }

    // ------------- Epilogue: in-register halves add, direct STG.64 ------------------
    // Thread owns D2 rows k = 16mw+g, 16mw+g+8 (hi) and +32 (lo); cols j = 32nw+8nt+2t,+1.
    // out[h, 64k + j] = hi + lo.
    {
        const int k0 = 16*mw + g;
        float* po = out + (size_t)h*LLEN + 32*nw + 2*t;
        #pragma unroll
        for (int nt = 0; nt < 4; nt++) {
            float2 v0, v1;
            v0.x = acc[0][nt][0] + acc[1][nt][0];
            v0.y = acc[0][nt][1] + acc[1][nt][1];
            v1.x = acc[0][nt][2] + acc[1][nt][2];
            v1.y = acc[0][nt][3] + acc[1][nt][3];
            *reinterpret_cast<float2*>(po + (size_t)k0*64 + 8*nt)       = v0;
            *reinterpret_cast<float2*>(po + (size_t)(k0+8)*64 + 8*nt)   = v1;
        }
    }
}

extern "C" void kernel_launch(void* const* d_in, const int* in_sizes, int n_in,
                              void* d_out, int out_size)
{
    const float* log_dt     = (const float*)d_in[0];
    const float* log_w_real = (const float*)d_in[1];
    const float* w_imag     = (const float*)d_in[2];
    const float* C_re       = (const float*)d_in[3];
    const float* C_im       = (const float*)d_in[4];
    float* out = (float*)d_out;

    cudaFuncSetAttribute(ssk_diag_kernel,
                         cudaFuncAttributeMaxDynamicSharedMemorySize, SM_TOTAL);

    ssk_diag_kernel<<<HDIM, 128, SM_TOTAL>>>(log_dt, log_w_real, w_imag,
                                             C_re, C_im, out);
}